// round 7
// baseline (speedup 1.0000x reference)
#include <cuda_runtime.h>
#include <cuda_bf16.h>
#include <math.h>
#include <stdint.h>

// ---------------- problem constants ----------------
#define BB    2
#define SS    2048
#define DIM   2048
#define HH    16
#define NOPE  128
#define ROPE  64
#define QKHD  192
#define VHD   128
#define KVRANK 512
#define ROWS  (BB*SS)             // 4096
#define QCOLS (HH*QKHD)           // 3072
#define KVCOLS (KVRANK + HH*ROPE) // 1536

// ---------------- scratch (device globals) ----------------------------------
__device__ float g_q  [ROWS * QCOLS];
__device__ float g_kv [ROWS * KVCOLS];
__device__ float g_c  [ROWS * KVRANK];     // tf32, k-permuted (GEMM Act input)
__device__ float g_kn [ROWS * HH * NOPE];
__device__ float g_v  [ROWS * HH * VHD];
__device__ float g_K  [ROWS * HH * QKHD];
__device__ float g_O  [ROWS * HH * VHD];   // tf32, k-permuted (GEMM Act input)
// tf32-rounded, transposed ([N][K]) and k-permuted weights; permuted x
__device__ float g_xt   [ROWS * DIM];
__device__ float g_wqt  [QCOLS * DIM];
__device__ float g_wkvt [KVCOLS * DIM];
__device__ float g_wkt  [HH * NOPE * KVRANK];
__device__ float g_wvt  [HH * VHD * KVRANK];
__device__ float g_wot  [DIM * HH * VHD];

// ---------------- tf32 helpers ----------------------------------------------
__device__ __forceinline__ uint32_t f2tf32(float f) {
    uint32_t r;
    asm("cvt.rna.tf32.f32 %0, %1;" : "=r"(r) : "f"(f));
    return r;
}
__device__ __forceinline__ float f2tf32f(float f) {
    return __uint_as_float(f2tf32(f));
}
__device__ __forceinline__ void mma_tf32(float* d, const uint32_t* a, const uint32_t* b) {
    asm volatile(
        "mma.sync.aligned.m16n8k8.row.col.f32.tf32.tf32.f32 "
        "{%0,%1,%2,%3}, {%4,%5,%6,%7}, {%8,%9}, {%0,%1,%2,%3};"
        : "+f"(d[0]), "+f"(d[1]), "+f"(d[2]), "+f"(d[3])
        : "r"(a[0]), "r"(a[1]), "r"(a[2]), "r"(a[3]), "r"(b[0]), "r"(b[1]));
}
// k-permutation within a 32-block: k' = (k&3)*8 + (k>>2)
__device__ __forceinline__ int kperm(int k) {
    return (k & ~31) + ((k & 3) << 3) + ((k & 31) >> 2);
}

// ---------------- prep: round+permute activation x ---------------------------
__global__ void permute_act_kernel(const float* __restrict__ src,
                                   float* __restrict__ dst, int K, int n4)
{
    int i = blockIdx.x * blockDim.x + threadIdx.x;
    if (i >= n4) return;
    int flat = i * 4;
    int row = flat / K, k = flat % K;       // k multiple of 4
    float4 v = *(const float4*)&src[flat];
    int base = row * K + (k & ~31) + ((k & 31) >> 2);
    dst[base]      = f2tf32f(v.x);
    dst[base + 8]  = f2tf32f(v.y);
    dst[base + 16] = f2tf32f(v.z);
    dst[base + 24] = f2tf32f(v.w);
}

// ---------------- prep: transpose+round+permute weights ----------------------
// W[K][N] -> Wt[N][K] with per-32-block k-permutation.
__global__ void transpose_w_kernel(const float* __restrict__ W,
                                   float* __restrict__ Wt, int K, int N)
{
    __shared__ float t[32][33];
    const int kb0 = blockIdx.y * 32;
    const int nb0 = blockIdx.x * 32;
    const int tid = threadIdx.x;   // 256
    #pragma unroll
    for (int it = 0; it < 4; it++) {
        int kl = (tid >> 5) + it * 8;
        int nl = tid & 31;
        t[kl][nl] = W[(size_t)(kb0 + kl) * N + nb0 + nl];
    }
    __syncthreads();
    #pragma unroll
    for (int it = 0; it < 4; it++) {
        int nl = (tid >> 5) + it * 8;
        int kl = tid & 31;
        int kp = ((kl & 3) << 3) + (kl >> 2);
        Wt[(size_t)(nb0 + nl) * K + kb0 + kp] = f2tf32f(t[kl][nl]);
    }
}

// ---------------- tf32 tensor-core GEMM (vectorized fragments) --------------
// C[M][N] = Act[M][K] @ W  where Wt = W^T [N][K]; both k-permuted tf32.
// 128x128x32 tile, 256 threads; warp = 32n x 64m; all fragment loads LDS.128.
#define GBM 128
#define GBN 128
#define GBK 32
#define TPAD 36
#define TILE_STAGE (128 * TPAD)
#define GEMM_SMEM ((4 * TILE_STAGE) * sizeof(float))

__global__ __launch_bounds__(256, 2)
void gemm_tf32_kernel(const float* __restrict__ Wt, const float* __restrict__ Act,
                      const float* __restrict__ bias, float* __restrict__ C,
                      int M, int N, int K)
{
    extern __shared__ float sg[];
    float* Ws = sg;                    // [2][128][TPAD]
    float* As = sg + 2 * TILE_STAGE;   // [2][128][TPAD]

    const int tid  = threadIdx.x;
    const int lane = tid & 31;
    const int warp = tid >> 5;
    const int g   = lane >> 2;
    const int tg  = lane & 3;
    const int wn2 = warp & 3;          // n-offset wn2*32
    const int wm2 = warp >> 2;         // m-offset wm2*64
    const int n0 = blockIdx.x * GBN;
    const int m0 = blockIdx.y * GBM;

    const uint32_t ws_base = (uint32_t)__cvta_generic_to_shared(Ws);
    const uint32_t as_base = (uint32_t)__cvta_generic_to_shared(As);

    float acc[2][8][4];
    #pragma unroll
    for (int nt = 0; nt < 2; nt++)
        #pragma unroll
        for (int mt = 0; mt < 8; mt++)
            #pragma unroll
            for (int i = 0; i < 4; i++) acc[nt][mt][i] = 0.f;

#define STAGE_LOAD(s_, kt_) do {                                               \
    const int r_ = tid >> 1;                                                   \
    const int cb_ = (tid & 1) * 16;                                            \
    _Pragma("unroll")                                                          \
    for (int j_ = 0; j_ < 4; j_++) {                                           \
        int c_ = cb_ + j_ * 4;                                                 \
        uint32_t dw_ = ws_base + (uint32_t)(((s_) * TILE_STAGE + r_ * TPAD + c_) * 4); \
        asm volatile("cp.async.cg.shared.global [%0], [%1], 16;"               \
                     :: "r"(dw_), "l"(Wt + (size_t)(n0 + r_) * K + (kt_) * GBK + c_)); \
        uint32_t da_ = as_base + (uint32_t)(((s_) * TILE_STAGE + r_ * TPAD + c_) * 4); \
        asm volatile("cp.async.cg.shared.global [%0], [%1], 16;"               \
                     :: "r"(da_), "l"(Act + (size_t)(m0 + r_) * K + (kt_) * GBK + c_)); \
    }                                                                          \
    asm volatile("cp.async.commit_group;");                                    \
} while (0)

    const int KT = K / GBK;
    STAGE_LOAD(0, 0);

    for (int kt = 0; kt < KT; kt++) {
        const int s = kt & 1;
        if (kt + 1 < KT) {
            STAGE_LOAD(1 - s, kt + 1);
            asm volatile("cp.async.wait_group 1;");
        } else {
            asm volatile("cp.async.wait_group 0;");
        }
        __syncthreads();

        const float* Wsl = Ws + s * TILE_STAGE;
        const float* Asl = As + s * TILE_STAGE;

        // W-side fragments for the whole kt: 8 x LDS.128
        float4 wf[2][2][2];   // [nt2][row01][half]
        #pragma unroll
        for (int nt = 0; nt < 2; nt++) {
            int rw = wn2 * 32 + nt * 16 + g;
            wf[nt][0][0] = *(const float4*)&Wsl[rw * TPAD + tg * 8];
            wf[nt][0][1] = *(const float4*)&Wsl[rw * TPAD + tg * 8 + 4];
            wf[nt][1][0] = *(const float4*)&Wsl[(rw + 8) * TPAD + tg * 8];
            wf[nt][1][1] = *(const float4*)&Wsl[(rw + 8) * TPAD + tg * 8 + 4];
        }

        #pragma unroll
        for (int mt = 0; mt < 8; mt++) {
            int rm = wm2 * 64 + mt * 8 + g;
            float4 a0 = *(const float4*)&Asl[rm * TPAD + tg * 8];
            float4 a1 = *(const float4*)&Asl[rm * TPAD + tg * 8 + 4];
            #pragma unroll
            for (int ks = 0; ks < 4; ks++) {
                const float* ap = (ks < 2) ? (const float*)&a0 : (const float*)&a1;
                uint32_t bf[2];
                bf[0] = __float_as_uint(ap[(ks & 1) * 2]);
                bf[1] = __float_as_uint(ap[(ks & 1) * 2 + 1]);
                #pragma unroll
                for (int nt = 0; nt < 2; nt++) {
                    const float* w0 = (const float*)&wf[nt][0][ks >> 1];
                    const float* w1 = (const float*)&wf[nt][1][ks >> 1];
                    uint32_t af[4];
                    af[0] = __float_as_uint(w0[(ks & 1) * 2]);
                    af[1] = __float_as_uint(w1[(ks & 1) * 2]);
                    af[2] = __float_as_uint(w0[(ks & 1) * 2 + 1]);
                    af[3] = __float_as_uint(w1[(ks & 1) * 2 + 1]);
                    mma_tf32(acc[nt][mt], af, bf);
                }
            }
        }
        __syncthreads();
    }
#undef STAGE_LOAD

    // epilogue: D[n][m] -> C[m][n] + bias[n]
    #pragma unroll
    for (int nt = 0; nt < 2; nt++) {
        int n = n0 + wn2 * 32 + nt * 16 + g;
        float bn0 = bias[n], bn8 = bias[n + 8];
        #pragma unroll
        for (int mt = 0; mt < 8; mt++) {
            int m = m0 + wm2 * 64 + mt * 8 + 2 * tg;
            C[(size_t)m * N + n]           = acc[nt][mt][0] + bn0;
            C[(size_t)(m + 1) * N + n]     = acc[nt][mt][1] + bn0;
            C[(size_t)m * N + n + 8]       = acc[nt][mt][2] + bn8;
            C[(size_t)(m + 1) * N + n + 8] = acc[nt][mt][3] + bn8;
        }
    }
}

// ---------------- LayerNorm (tf32-rounded, k-permuted output) ---------------
__global__ void ln_kernel(const float* __restrict__ kv,
                          const float* __restrict__ gamma,
                          const float* __restrict__ beta,
                          float* __restrict__ out)
{
    const int row = blockIdx.x;
    const float* src = kv + (size_t)row * KVCOLS + HH * ROPE;
    float* dst = out + (size_t)row * KVRANK;
    const int tid = threadIdx.x;

    float v[4];
    float s = 0.f, s2 = 0.f;
    #pragma unroll
    for (int i = 0; i < 4; i++) {
        v[i] = src[tid + i * 128];
        s += v[i];
        s2 += v[i] * v[i];
    }
    __shared__ float rs[128], rs2[128];
    rs[tid] = s; rs2[tid] = s2;
    __syncthreads();
    for (int o = 64; o > 0; o >>= 1) {
        if (tid < o) { rs[tid] += rs[tid + o]; rs2[tid] += rs2[tid + o]; }
        __syncthreads();
    }
    float mean = rs[0] * (1.f / 512.f);
    float var  = rs2[0] * (1.f / 512.f) - mean * mean;
    float rstd = rsqrtf(var + 1e-5f);
    #pragma unroll
    for (int i = 0; i < 4; i++) {
        int c = tid + i * 128;
        dst[kperm(c)] = f2tf32f((v[i] - mean) * rstd * gamma[c] + beta[c]);
    }
}

// ---------------- RoPE + K assembly (REFERENCE reshape semantics) -----------
__global__ void rope_assemble_kernel(float* __restrict__ q,
                                     const float* __restrict__ kv,
                                     const float* __restrict__ knope,
                                     const float* __restrict__ cosT,
                                     const float* __restrict__ sinT,
                                     float* __restrict__ Kout)
{
    int idx = blockIdx.x * blockDim.x + threadIdx.x;
    if (idx >= ROWS * HH * 32) return;
    int p   = idx & 31;
    int h   = (idx >> 5) & 15;
    int row = idx >> 9;
    int s   = row & (SS - 1);

    float cv = cosT[s * 32 + p];
    float sv = sinT[s * 32 + p];

    size_t qb = (size_t)row * QCOLS + h * QKHD + NOPE + 2 * p;
    float a = q[qb], b = q[qb + 1];
    q[qb]     = a * cv - b * sv;
    q[qb + 1] = a * sv + b * cv;

    const float* knr = knope + (size_t)row * (HH * NOPE);
    const float* krr = kv + (size_t)row * KVCOLS;
    size_t ko = ((size_t)row * HH + h) * QKHD;

    {
        int gg = h * QKHD + p * 4;
        float4 nv;
        if (gg < HH * NOPE) nv = *(const float4*)&knr[gg];
        else                nv = *(const float4*)&krr[gg - HH * NOPE];
        *(float4*)&Kout[ko + p * 4] = nv;
    }
    {
        int gg = h * QKHD + NOPE + 2 * p;
        float ka, kb;
        if (gg < HH * NOPE) { ka = knr[gg];              kb = knr[gg + 1]; }
        else                { ka = krr[gg - HH * NOPE];  kb = krr[gg - HH * NOPE + 1]; }
        Kout[ko + NOPE + 2 * p]     = ka * cv - kb * sv;
        Kout[ko + NOPE + 2 * p + 1] = ka * sv + kb * cv;
    }
}

// ---------------- tf32 tensor-core causal flash attention -------------------
#define ABQ 64
#define ABK 64
#define QSP 196
#define KSP 196
#define VSP 136
#define PSP 68
#define OSP 132
#define ATTN_SMEM ((ABQ*QSP + ABK*KSP + ABK*VSP + ABQ*PSP) * sizeof(float))

__global__ __launch_bounds__(256, 1)
void attn_mma_kernel(const float* __restrict__ Q,
                     const float* __restrict__ Kf,
                     const float* __restrict__ V,
                     float* __restrict__ O)
{
    const int q0 = blockIdx.x * ABQ;
    const int h  = blockIdx.y;
    const int b  = blockIdx.z;

    extern __shared__ float sm[];
    float* Qs = sm;
    float* Ks = Qs + ABQ * QSP;
    float* Vs = Ks + ABK * KSP;
    float* Ps = Vs + ABK * VSP;

    const int tid  = threadIdx.x;
    const int lane = tid & 31;
    const int wid  = tid >> 5;
    const int g    = lane >> 2;
    const int tg   = lane & 3;
    const int wq   = wid & 3;
    const int kh   = wid >> 2;
    const int rA   = wq * 16 + g;
    const float scale = 0.07216878364870322f;

    const float* Qg = Q + (((size_t)(b * SS + q0)) * HH + h) * QKHD;
    #pragma unroll
    for (int n = 0; n < 12; n++) {
        int i = tid + n * 256;
        int r = i / 48, d4 = (i % 48) * 4;
        float4 v = *(const float4*)&Qg[(size_t)r * (HH * QKHD) + d4];
        v.x = f2tf32f(v.x * scale); v.y = f2tf32f(v.y * scale);
        v.z = f2tf32f(v.z * scale); v.w = f2tf32f(v.w * scale);
        *(float4*)&Qs[r * QSP + d4] = v;
    }

    float m0 = -INFINITY, m1 = -INFINITY, l0 = 0.f, l1 = 0.f;
    float acc[16][4];
    #pragma unroll
    for (int nt = 0; nt < 16; nt++)
        #pragma unroll
        for (int i = 0; i < 4; i++) acc[nt][i] = 0.f;

    const int jend = blockIdx.x;
    for (int j = 0; j <= jend; j++) {
        const int k0 = j * ABK;
        __syncthreads();
        const float* Kg = Kf + (((size_t)(b * SS + k0)) * HH + h) * QKHD;
        #pragma unroll
        for (int n = 0; n < 12; n++) {
            int i = tid + n * 256;
            int r = i / 48, d4 = (i % 48) * 4;
            float4 v = *(const float4*)&Kg[(size_t)r * (HH * QKHD) + d4];
            v.x = f2tf32f(v.x); v.y = f2tf32f(v.y);
            v.z = f2tf32f(v.z); v.w = f2tf32f(v.w);
            *(float4*)&Ks[r * KSP + d4] = v;
        }
        const float* Vg = V + (((size_t)(b * SS + k0)) * HH + h) * VHD;
        #pragma unroll
        for (int n = 0; n < 8; n++) {
            int i = tid + n * 256;
            int r = i / 32, d4 = (i % 32) * 4;
            float4 v = *(const float4*)&Vg[(size_t)r * (HH * VHD) + d4];
            v.x = f2tf32f(v.x); v.y = f2tf32f(v.y);
            v.z = f2tf32f(v.z); v.w = f2tf32f(v.w);
            *(float4*)&Vs[r * VSP + d4] = v;
        }
        __syncthreads();

        float sc[4][4];
        #pragma unroll
        for (int nt = 0; nt < 4; nt++)
            #pragma unroll
            for (int i = 0; i < 4; i++) sc[nt][i] = 0.f;

        #pragma unroll
        for (int kc = 0; kc < 24; kc++) {
            uint32_t af[4];
            af[0] = __float_as_uint(Qs[rA * QSP + kc * 8 + tg]);
            af[1] = __float_as_uint(Qs[(rA + 8) * QSP + kc * 8 + tg]);
            af[2] = __float_as_uint(Qs[rA * QSP + kc * 8 + tg + 4]);
            af[3] = __float_as_uint(Qs[(rA + 8) * QSP + kc * 8 + tg + 4]);
            #pragma unroll
            for (int nt = 0; nt < 4; nt++) {
                int kvr = kh * 32 + nt * 8 + g;
                uint32_t bf[2];
                bf[0] = __float_as_uint(Ks[kvr * KSP + kc * 8 + tg]);
                bf[1] = __float_as_uint(Ks[kvr * KSP + kc * 8 + tg + 4]);
                mma_tf32(sc[nt], af, bf);
            }
        }

        if (j == jend) {
            #pragma unroll
            for (int nt = 0; nt < 4; nt++) {
                int colb = k0 + kh * 32 + nt * 8 + 2 * tg;
                int row0g = q0 + rA, row1g = q0 + rA + 8;
                if (colb     > row0g) sc[nt][0] = -INFINITY;
                if (colb + 1 > row0g) sc[nt][1] = -INFINITY;
                if (colb     > row1g) sc[nt][2] = -INFINITY;
                if (colb + 1 > row1g) sc[nt][3] = -INFINITY;
            }
        }

        float ml0 = -INFINITY, ml1 = -INFINITY;
        #pragma unroll
        for (int nt = 0; nt < 4; nt++) {
            ml0 = fmaxf(ml0, fmaxf(sc[nt][0], sc[nt][1]));
            ml1 = fmaxf(ml1, fmaxf(sc[nt][2], sc[nt][3]));
        }
        ml0 = fmaxf(ml0, __shfl_xor_sync(0xffffffffu, ml0, 1));
        ml0 = fmaxf(ml0, __shfl_xor_sync(0xffffffffu, ml0, 2));
        ml1 = fmaxf(ml1, __shfl_xor_sync(0xffffffffu, ml1, 1));
        ml1 = fmaxf(ml1, __shfl_xor_sync(0xffffffffu, ml1, 2));
        float mn0 = fmaxf(m0, ml0), mn1 = fmaxf(m1, ml1);
        float mr0 = (mn0 == -INFINITY) ? 0.f : mn0;
        float mr1 = (mn1 == -INFINITY) ? 0.f : mn1;
        float a0 = __expf(m0 - mr0);
        float a1 = __expf(m1 - mr1);

        float ll0 = 0.f, ll1 = 0.f;
        #pragma unroll
        for (int nt = 0; nt < 4; nt++) {
            float p0 = __expf(sc[nt][0] - mr0);
            float p1 = __expf(sc[nt][1] - mr0);
            float p2 = __expf(sc[nt][2] - mr1);
            float p3 = __expf(sc[nt][3] - mr1);
            ll0 += p0 + p1;
            ll1 += p2 + p3;
            int cb = kh * 32 + nt * 8 + 2 * tg;
            *(float2*)&Ps[rA * PSP + cb]       = make_float2(f2tf32f(p0), f2tf32f(p1));
            *(float2*)&Ps[(rA + 8) * PSP + cb] = make_float2(f2tf32f(p2), f2tf32f(p3));
        }
        ll0 += __shfl_xor_sync(0xffffffffu, ll0, 1);
        ll0 += __shfl_xor_sync(0xffffffffu, ll0, 2);
        ll1 += __shfl_xor_sync(0xffffffffu, ll1, 1);
        ll1 += __shfl_xor_sync(0xffffffffu, ll1, 2);

        m0 = mn0; m1 = mn1;
        l0 = l0 * a0 + ll0;
        l1 = l1 * a1 + ll1;

        #pragma unroll
        for (int nt = 0; nt < 16; nt++) {
            acc[nt][0] *= a0; acc[nt][1] *= a0;
            acc[nt][2] *= a1; acc[nt][3] *= a1;
        }
        __syncwarp();

        #pragma unroll
        for (int kc = 0; kc < 4; kc++) {
            uint32_t af[4];
            int pc = kh * 32 + kc * 8;
            af[0] = __float_as_uint(Ps[rA * PSP + pc + tg]);
            af[1] = __float_as_uint(Ps[(rA + 8) * PSP + pc + tg]);
            af[2] = __float_as_uint(Ps[rA * PSP + pc + tg + 4]);
            af[3] = __float_as_uint(Ps[(rA + 8) * PSP + pc + tg + 4]);
            int kv0 = kh * 32 + kc * 8 + tg;
            #pragma unroll
            for (int nt = 0; nt < 16; nt++) {
                uint32_t bf[2];
                bf[0] = __float_as_uint(Vs[kv0 * VSP + nt * 8 + g]);
                bf[1] = __float_as_uint(Vs[(kv0 + 4) * VSP + nt * 8 + g]);
                mma_tf32(acc[nt], af, bf);
            }
        }
        __syncwarp();
    }

    // ---- merge kv halves; write tf32-rounded, k-permuted O ----
    __syncthreads();
    float* Osh = Ks;
    float* msh = Ps;
    float* lsh = Ps + 64;

    if (kh == 1) {
        if (tg == 0) {
            msh[rA] = m0;  msh[rA + 8] = m1;
            lsh[rA] = l0;  lsh[rA + 8] = l1;
        }
        #pragma unroll
        for (int nt = 0; nt < 16; nt++) {
            int cb = nt * 8 + 2 * tg;
            *(float2*)&Osh[rA * OSP + cb]       = make_float2(acc[nt][0], acc[nt][1]);
            *(float2*)&Osh[(rA + 8) * OSP + cb] = make_float2(acc[nt][2], acc[nt][3]);
        }
    }
    __syncthreads();
    if (kh == 0) {
        float mB0 = msh[rA], mB1 = msh[rA + 8];
        float lB0 = lsh[rA], lB1 = lsh[rA + 8];
        float mm0 = fmaxf(m0, mB0), mm1 = fmaxf(m1, mB1);
        float wA0 = __expf(m0 - mm0),  wB0 = __expf(mB0 - mm0);
        float wA1 = __expf(m1 - mm1),  wB1 = __expf(mB1 - mm1);
        float inv0 = 1.f / (wA0 * l0 + wB0 * lB0);
        float inv1 = 1.f / (wA1 * l1 + wB1 * lB1);

        size_t ob0 = (((size_t)(b * SS + q0 + rA)) * HH + h) * VHD;
        size_t ob1 = (((size_t)(b * SS + q0 + rA + 8)) * HH + h) * VHD;
        #pragma unroll
        for (int nt = 0; nt < 16; nt++) {
            int cb = nt * 8 + 2 * tg;
            float2 oB0 = *(float2*)&Osh[rA * OSP + cb];
            float2 oB1 = *(float2*)&Osh[(rA + 8) * OSP + cb];
            int p0 = kperm(cb), p1 = kperm(cb + 1);
            O[ob0 + p0] = f2tf32f((wA0 * acc[nt][0] + wB0 * oB0.x) * inv0);
            O[ob0 + p1] = f2tf32f((wA0 * acc[nt][1] + wB0 * oB0.y) * inv0);
            O[ob1 + p0] = f2tf32f((wA1 * acc[nt][2] + wB1 * oB1.x) * inv1);
            O[ob1 + p1] = f2tf32f((wA1 * acc[nt][3] + wB1 * oB1.y) * inv1);
        }
    }
}

// ---------------- launch -----------------------------------------------------
extern "C" void kernel_launch(void* const* d_in, const int* in_sizes, int n_in,
                              void* d_out, int out_size)
{
    const float* x       = (const float*)d_in[0];
    const float* wq_w    = (const float*)d_in[1];
    const float* wq_b    = (const float*)d_in[2];
    const float* wkv_a_w = (const float*)d_in[3];
    const float* wkv_a_b = (const float*)d_in[4];
    const float* kvn_g   = (const float*)d_in[5];
    const float* kvn_b   = (const float*)d_in[6];
    const float* wk_w    = (const float*)d_in[7];
    const float* wk_b    = (const float*)d_in[8];
    const float* wv_w    = (const float*)d_in[9];
    const float* wv_b    = (const float*)d_in[10];
    const float* wo_w    = (const float*)d_in[11];
    const float* wo_b    = (const float*)d_in[12];
    const float* cosT    = (const float*)d_in[13];
    const float* sinT    = (const float*)d_in[14];
    float* out = (float*)d_out;

    float *gq, *gkv, *gc, *gkn, *gv, *gK, *gO;
    float *xt, *wqt, *wkvt, *wkt, *wvt, *wot;
    cudaGetSymbolAddress((void**)&gq,   g_q);
    cudaGetSymbolAddress((void**)&gkv,  g_kv);
    cudaGetSymbolAddress((void**)&gc,   g_c);
    cudaGetSymbolAddress((void**)&gkn,  g_kn);
    cudaGetSymbolAddress((void**)&gv,   g_v);
    cudaGetSymbolAddress((void**)&gK,   g_K);
    cudaGetSymbolAddress((void**)&gO,   g_O);
    cudaGetSymbolAddress((void**)&xt,   g_xt);
    cudaGetSymbolAddress((void**)&wqt,  g_wqt);
    cudaGetSymbolAddress((void**)&wkvt, g_wkvt);
    cudaGetSymbolAddress((void**)&wkt,  g_wkt);
    cudaGetSymbolAddress((void**)&wvt,  g_wvt);
    cudaGetSymbolAddress((void**)&wot,  g_wot);

    cudaFuncSetAttribute(gemm_tf32_kernel, cudaFuncAttributeMaxDynamicSharedMemorySize, (int)GEMM_SMEM);
    cudaFuncSetAttribute(attn_mma_kernel, cudaFuncAttributeMaxDynamicSharedMemorySize, (int)ATTN_SMEM);

    // 0a) permute+round x
    {
        int n4 = ROWS * DIM / 4;
        permute_act_kernel<<<(n4 + 255) / 256, 256>>>(x, xt, DIM, n4);
    }
    // 0b) transpose+round+permute weights  W[K][N] -> Wt[N][K]
    transpose_w_kernel<<<dim3(QCOLS/32,  DIM/32),    256>>>(wq_w,    wqt,  DIM,    QCOLS);
    transpose_w_kernel<<<dim3(KVCOLS/32, DIM/32),    256>>>(wkv_a_w, wkvt, DIM,    KVCOLS);
    transpose_w_kernel<<<dim3((HH*NOPE)/32, KVRANK/32), 256>>>(wk_w, wkt,  KVRANK, HH*NOPE);
    transpose_w_kernel<<<dim3((HH*VHD)/32,  KVRANK/32), 256>>>(wv_w, wvt,  KVRANK, HH*VHD);
    transpose_w_kernel<<<dim3(DIM/32, (HH*VHD)/32),  256>>>(wo_w,    wot,  HH*VHD, DIM);

    // 1) q = x @ wq_w + b
    gemm_tf32_kernel<<<dim3(QCOLS/GBN, ROWS/GBM), 256, GEMM_SMEM>>>(wqt, xt, wq_b, gq, ROWS, QCOLS, DIM);
    // 2) kv = x @ wkv_a_w + b
    gemm_tf32_kernel<<<dim3(KVCOLS/GBN, ROWS/GBM), 256, GEMM_SMEM>>>(wkvt, xt, wkv_a_b, gkv, ROWS, KVCOLS, DIM);
    // 3) layernorm (tf32, k-permuted output)
    ln_kernel<<<ROWS, 128>>>(gkv, kvn_g, kvn_b, gc);
    // 4) k_nope = c @ wk_w + b
    gemm_tf32_kernel<<<dim3((HH*NOPE)/GBN, ROWS/GBM), 256, GEMM_SMEM>>>(wkt, gc, wk_b, gkn, ROWS, HH*NOPE, KVRANK);
    // 5) v = c @ wv_w + b
    gemm_tf32_kernel<<<dim3((HH*VHD)/GBN, ROWS/GBM), 256, GEMM_SMEM>>>(wvt, gc, wv_b, gv, ROWS, HH*VHD, KVRANK);
    // 6) rope + assemble K
    {
        int total = ROWS * HH * 32;
        rope_assemble_kernel<<<(total + 255) / 256, 256>>>(gq, gkv, gkn, cosT, sinT, gK);
    }
    // 7) attention (tf32 mma; emits tf32-rounded k-permuted O)
    attn_mma_kernel<<<dim3(SS/ABQ, HH, BB), 256, ATTN_SMEM>>>(gq, gK, gv, gO);
    // 8) out = O @ wo_w + b
    gemm_tf32_kernel<<<dim3(DIM/GBN, ROWS/GBM), 256, GEMM_SMEM>>>(wot, gO, wo_b, out, ROWS, DIM, HH*VHD);
}

// round 8
// speedup vs baseline: 1.3694x; 1.3694x over previous
#include <cuda_runtime.h>
#include <cuda_bf16.h>
#include <math.h>
#include <stdint.h>

// ---------------- problem constants ----------------
#define BB    2
#define SS    2048
#define DIM   2048
#define HH    16
#define NOPE  128
#define ROPE  64
#define QKHD  192
#define VHD   128
#define KVRANK 512
#define ROWS  (BB*SS)             // 4096
#define QCOLS (HH*QKHD)           // 3072
#define KVCOLS (KVRANK + HH*ROPE) // 1536

// ---------------- scratch (device globals) ----------------------------------
__device__ float g_q  [ROWS * QCOLS];
__device__ float g_kv [ROWS * KVCOLS];
__device__ float g_c  [ROWS * KVRANK];     // tf32-rounded latent (GEMM Act input)
__device__ float g_kn [ROWS * HH * NOPE];
__device__ float g_v  [ROWS * HH * VHD];
__device__ float g_K  [ROWS * HH * QKHD];
__device__ float g_O  [ROWS * HH * VHD];   // tf32-rounded attention out (GEMM Act input)
// tf32-rounded x; transposed ([N][K]) + k-permuted tf32 weights
__device__ float g_xt   [ROWS * DIM];
__device__ float g_wqt  [QCOLS * DIM];
__device__ float g_wkvt [KVCOLS * DIM];
__device__ float g_wkt  [HH * NOPE * KVRANK];
__device__ float g_wvt  [HH * VHD * KVRANK];
__device__ float g_wot  [DIM * HH * VHD];

// ---------------- tf32 helpers ----------------------------------------------
__device__ __forceinline__ uint32_t f2tf32(float f) {
    uint32_t r;
    asm("cvt.rna.tf32.f32 %0, %1;" : "=r"(r) : "f"(f));
    return r;
}
__device__ __forceinline__ float f2tf32f(float f) {
    return __uint_as_float(f2tf32(f));
}
__device__ __forceinline__ void mma_tf32(float* d, const uint32_t* a, const uint32_t* b) {
    asm volatile(
        "mma.sync.aligned.m16n8k8.row.col.f32.tf32.tf32.f32 "
        "{%0,%1,%2,%3}, {%4,%5,%6,%7}, {%8,%9}, {%0,%1,%2,%3};"
        : "+f"(d[0]), "+f"(d[1]), "+f"(d[2]), "+f"(d[3])
        : "r"(a[0]), "r"(a[1]), "r"(a[2]), "r"(a[3]), "r"(b[0]), "r"(b[1]));
}

// ---------------- prep: tf32 round (plain layout, for activations) ----------
__global__ void tf32_convert_kernel(const float* __restrict__ src,
                                    float* __restrict__ dst, int n4)
{
    int i = blockIdx.x * blockDim.x + threadIdx.x;
    if (i >= n4) return;
    float4 v = *(const float4*)&src[i * 4];
    v.x = f2tf32f(v.x); v.y = f2tf32f(v.y);
    v.z = f2tf32f(v.z); v.w = f2tf32f(v.w);
    *(float4*)&dst[i * 4] = v;
}

// ---------------- prep: transpose+round+k-permute weights -------------------
// W[K][N] -> Wt[N][K], k' within each 32-block = (k&3)*8 + (k>>2).
__global__ void transpose_w_kernel(const float* __restrict__ W,
                                   float* __restrict__ Wt, int K, int N)
{
    __shared__ float t[32][33];
    const int kb0 = blockIdx.y * 32;
    const int nb0 = blockIdx.x * 32;
    const int tid = threadIdx.x;   // 256
    #pragma unroll
    for (int it = 0; it < 4; it++) {
        int kl = (tid >> 5) + it * 8;
        int nl = tid & 31;
        t[kl][nl] = W[(size_t)(kb0 + kl) * N + nb0 + nl];
    }
    __syncthreads();
    #pragma unroll
    for (int it = 0; it < 4; it++) {
        int nl = (tid >> 5) + it * 8;
        int kl = tid & 31;
        int kp = ((kl & 3) << 3) + (kl >> 2);
        Wt[(size_t)(nb0 + nl) * K + kb0 + kp] = f2tf32f(t[kl][nl]);
    }
}

// ---------------- tf32 tensor-core GEMM ------------------------------------
// C[M][N] = Act[M][K] @ W + bias.  Wt = W^T [N][K], k-permuted; Act plain.
// R6 thread mapping & epilogue; B fragments via LDS.128 from Wt tile.
#define GBM 128
#define GBN 128
#define GBK 32
#define TPAD 36
#define TILE_STAGE (128 * TPAD)
#define GEMM_SMEM ((4 * TILE_STAGE) * sizeof(float))

__global__ __launch_bounds__(256, 2)
void gemm_tf32_kernel(const float* __restrict__ Wt, const float* __restrict__ Act,
                      const float* __restrict__ bias, float* __restrict__ C,
                      int M, int N, int K)
{
    extern __shared__ float sg[];
    float* As = sg;                    // [2][128 m][TPAD]  (plain k order)
    float* Ws = sg + 2 * TILE_STAGE;   // [2][128 n][TPAD]  (k-permuted)
    const uint32_t* Asu = (const uint32_t*)As;

    const int tid  = threadIdx.x;
    const int lane = tid & 31;
    const int warp = tid >> 5;
    const int g  = lane >> 2;
    const int tg = lane & 3;
    const int wm = warp & 3;           // warp m-offset wm*32
    const int wn = warp >> 2;          // warp n-offset wn*64
    const int row0 = blockIdx.y * GBM;
    const int col0 = blockIdx.x * GBN;

    const uint32_t as_base = (uint32_t)__cvta_generic_to_shared(As);
    const uint32_t ws_base = (uint32_t)__cvta_generic_to_shared(Ws);

    float acc[2][8][4];
    #pragma unroll
    for (int mt = 0; mt < 2; mt++)
        #pragma unroll
        for (int nt = 0; nt < 8; nt++)
            #pragma unroll
            for (int i = 0; i < 4; i++) acc[mt][nt][i] = 0.f;

#define STAGE_LOAD(s_, kt_) do {                                               \
    _Pragma("unroll")                                                          \
    for (int n_ = 0; n_ < 4; n_++) {                                           \
        int i_ = tid + n_ * 256; int r_ = i_ >> 3; int c_ = (i_ & 7) * 4;      \
        uint32_t da_ = as_base + (uint32_t)(((s_) * TILE_STAGE + r_ * TPAD + c_) * 4); \
        asm volatile("cp.async.cg.shared.global [%0], [%1], 16;"               \
                     :: "r"(da_), "l"(Act + (size_t)(row0 + r_) * K + (kt_) * GBK + c_)); \
        uint32_t dw_ = ws_base + (uint32_t)(((s_) * TILE_STAGE + r_ * TPAD + c_) * 4); \
        asm volatile("cp.async.cg.shared.global [%0], [%1], 16;"               \
                     :: "r"(dw_), "l"(Wt + (size_t)(col0 + r_) * K + (kt_) * GBK + c_)); \
    }                                                                          \
    asm volatile("cp.async.commit_group;");                                    \
} while (0)

    const int KT = K / GBK;
    STAGE_LOAD(0, 0);

    for (int kt = 0; kt < KT; kt++) {
        const int s = kt & 1;
        if (kt + 1 < KT) {
            STAGE_LOAD(1 - s, kt + 1);
            asm volatile("cp.async.wait_group 1;");
        } else {
            asm volatile("cp.async.wait_group 0;");
        }
        __syncthreads();

        const uint32_t* Asl = Asu + s * TILE_STAGE;
        const float*    Wsl = Ws  + s * TILE_STAGE;

        #pragma unroll
        for (int hp = 0; hp < 2; hp++) {           // ks pair {2hp, 2hp+1}
            // A fragments for these 2 k-steps (plain k order)
            uint32_t af[2][2][4];
            #pragma unroll
            for (int ksl = 0; ksl < 2; ksl++) {
                const int kc = (hp * 2 + ksl) * 8 + tg;
                #pragma unroll
                for (int mt = 0; mt < 2; mt++) {
                    int row = wm * 32 + mt * 16 + g;
                    af[ksl][mt][0] = Asl[row * TPAD + kc];
                    af[ksl][mt][1] = Asl[(row + 8) * TPAD + kc];
                    af[ksl][mt][2] = Asl[row * TPAD + kc + 4];
                    af[ksl][mt][3] = Asl[(row + 8) * TPAD + kc + 4];
                }
            }
            #pragma unroll
            for (int nt = 0; nt < 8; nt++) {
                int col = wn * 64 + nt * 8 + g;
                float4 w = *(const float4*)&Wsl[col * TPAD + 8 * tg + 4 * hp];
                const uint32_t* wu = (const uint32_t*)&w;
                #pragma unroll
                for (int ksl = 0; ksl < 2; ksl++) {
                    uint32_t bf[2] = { wu[2 * ksl], wu[2 * ksl + 1] };
                    #pragma unroll
                    for (int mt = 0; mt < 2; mt++)
                        mma_tf32(acc[mt][nt], af[ksl][mt], bf);
                }
            }
        }
        __syncthreads();
    }
#undef STAGE_LOAD

    // epilogue (R6): C[m][n] float2 along n
    #pragma unroll
    for (int mt = 0; mt < 2; mt++) {
        int r = row0 + wm * 32 + mt * 16 + g;
        #pragma unroll
        for (int nt = 0; nt < 8; nt++) {
            int c = col0 + wn * 64 + nt * 8 + tg * 2;
            float b0 = bias[c], b1 = bias[c + 1];
            float2 v0 = make_float2(acc[mt][nt][0] + b0, acc[mt][nt][1] + b1);
            float2 v1 = make_float2(acc[mt][nt][2] + b0, acc[mt][nt][3] + b1);
            *(float2*)&C[(size_t)r * N + c]       = v0;
            *(float2*)&C[(size_t)(r + 8) * N + c] = v1;
        }
    }
}

// ---------------- LayerNorm (tf32-rounded output, plain layout) -------------
__global__ void ln_kernel(const float* __restrict__ kv,
                          const float* __restrict__ gamma,
                          const float* __restrict__ beta,
                          float* __restrict__ out)
{
    const int row = blockIdx.x;
    const float* src = kv + (size_t)row * KVCOLS + HH * ROPE;
    float* dst = out + (size_t)row * KVRANK;
    const int tid = threadIdx.x;

    float v[4];
    float s = 0.f, s2 = 0.f;
    #pragma unroll
    for (int i = 0; i < 4; i++) {
        v[i] = src[tid + i * 128];
        s += v[i];
        s2 += v[i] * v[i];
    }
    __shared__ float rs[128], rs2[128];
    rs[tid] = s; rs2[tid] = s2;
    __syncthreads();
    for (int o = 64; o > 0; o >>= 1) {
        if (tid < o) { rs[tid] += rs[tid + o]; rs2[tid] += rs2[tid + o]; }
        __syncthreads();
    }
    float mean = rs[0] * (1.f / 512.f);
    float var  = rs2[0] * (1.f / 512.f) - mean * mean;
    float rstd = rsqrtf(var + 1e-5f);
    #pragma unroll
    for (int i = 0; i < 4; i++) {
        int c = tid + i * 128;
        dst[c] = f2tf32f((v[i] - mean) * rstd * gamma[c] + beta[c]);
    }
}

// ---------------- RoPE + K assembly (REFERENCE reshape semantics) -----------
__global__ void rope_assemble_kernel(float* __restrict__ q,
                                     const float* __restrict__ kv,
                                     const float* __restrict__ knope,
                                     const float* __restrict__ cosT,
                                     const float* __restrict__ sinT,
                                     float* __restrict__ Kout)
{
    int idx = blockIdx.x * blockDim.x + threadIdx.x;
    if (idx >= ROWS * HH * 32) return;
    int p   = idx & 31;
    int h   = (idx >> 5) & 15;
    int row = idx >> 9;
    int s   = row & (SS - 1);

    float cv = cosT[s * 32 + p];
    float sv = sinT[s * 32 + p];

    size_t qb = (size_t)row * QCOLS + h * QKHD + NOPE + 2 * p;
    float a = q[qb], b = q[qb + 1];
    q[qb]     = a * cv - b * sv;
    q[qb + 1] = a * sv + b * cv;

    const float* knr = knope + (size_t)row * (HH * NOPE);
    const float* krr = kv + (size_t)row * KVCOLS;
    size_t ko = ((size_t)row * HH + h) * QKHD;

    {
        int gg = h * QKHD + p * 4;
        float4 nv;
        if (gg < HH * NOPE) nv = *(const float4*)&knr[gg];
        else                nv = *(const float4*)&krr[gg - HH * NOPE];
        *(float4*)&Kout[ko + p * 4] = nv;
    }
    {
        int gg = h * QKHD + NOPE + 2 * p;
        float ka, kb;
        if (gg < HH * NOPE) { ka = knr[gg];              kb = knr[gg + 1]; }
        else                { ka = krr[gg - HH * NOPE];  kb = krr[gg - HH * NOPE + 1]; }
        Kout[ko + NOPE + 2 * p]     = ka * cv - kb * sv;
        Kout[ko + NOPE + 2 * p + 1] = ka * sv + kb * cv;
    }
}

// ---------------- tf32 tensor-core causal flash attention (R6) --------------
#define ABQ 64
#define ABK 64
#define QSP 196
#define KSP 196
#define VSP 136
#define PSP 68
#define OSP 132
#define ATTN_SMEM ((ABQ*QSP + ABK*KSP + ABK*VSP + ABQ*PSP) * sizeof(float))

__global__ __launch_bounds__(256, 1)
void attn_mma_kernel(const float* __restrict__ Q,
                     const float* __restrict__ Kf,
                     const float* __restrict__ V,
                     float* __restrict__ O)
{
    const int q0 = blockIdx.x * ABQ;
    const int h  = blockIdx.y;
    const int b  = blockIdx.z;

    extern __shared__ float sm[];
    float* Qs = sm;
    float* Ks = Qs + ABQ * QSP;
    float* Vs = Ks + ABK * KSP;
    float* Ps = Vs + ABK * VSP;

    const int tid  = threadIdx.x;
    const int lane = tid & 31;
    const int wid  = tid >> 5;
    const int g    = lane >> 2;
    const int tg   = lane & 3;
    const int wq   = wid & 3;
    const int kh   = wid >> 2;
    const int rA   = wq * 16 + g;
    const float scale = 0.07216878364870322f;

    const float* Qg = Q + (((size_t)(b * SS + q0)) * HH + h) * QKHD;
    #pragma unroll
    for (int n = 0; n < 12; n++) {
        int i = tid + n * 256;
        int r = i / 48, d4 = (i % 48) * 4;
        float4 v = *(const float4*)&Qg[(size_t)r * (HH * QKHD) + d4];
        v.x = f2tf32f(v.x * scale); v.y = f2tf32f(v.y * scale);
        v.z = f2tf32f(v.z * scale); v.w = f2tf32f(v.w * scale);
        *(float4*)&Qs[r * QSP + d4] = v;
    }

    float m0 = -INFINITY, m1 = -INFINITY, l0 = 0.f, l1 = 0.f;
    float acc[16][4];
    #pragma unroll
    for (int nt = 0; nt < 16; nt++)
        #pragma unroll
        for (int i = 0; i < 4; i++) acc[nt][i] = 0.f;

    const int jend = blockIdx.x;
    for (int j = 0; j <= jend; j++) {
        const int k0 = j * ABK;
        __syncthreads();
        const float* Kg = Kf + (((size_t)(b * SS + k0)) * HH + h) * QKHD;
        #pragma unroll
        for (int n = 0; n < 12; n++) {
            int i = tid + n * 256;
            int r = i / 48, d4 = (i % 48) * 4;
            float4 v = *(const float4*)&Kg[(size_t)r * (HH * QKHD) + d4];
            v.x = f2tf32f(v.x); v.y = f2tf32f(v.y);
            v.z = f2tf32f(v.z); v.w = f2tf32f(v.w);
            *(float4*)&Ks[r * KSP + d4] = v;
        }
        const float* Vg = V + (((size_t)(b * SS + k0)) * HH + h) * VHD;
        #pragma unroll
        for (int n = 0; n < 8; n++) {
            int i = tid + n * 256;
            int r = i / 32, d4 = (i % 32) * 4;
            float4 v = *(const float4*)&Vg[(size_t)r * (HH * VHD) + d4];
            v.x = f2tf32f(v.x); v.y = f2tf32f(v.y);
            v.z = f2tf32f(v.z); v.w = f2tf32f(v.w);
            *(float4*)&Vs[r * VSP + d4] = v;
        }
        __syncthreads();

        float sc[4][4];
        #pragma unroll
        for (int nt = 0; nt < 4; nt++)
            #pragma unroll
            for (int i = 0; i < 4; i++) sc[nt][i] = 0.f;

        #pragma unroll
        for (int kc = 0; kc < 24; kc++) {
            uint32_t af[4];
            af[0] = __float_as_uint(Qs[rA * QSP + kc * 8 + tg]);
            af[1] = __float_as_uint(Qs[(rA + 8) * QSP + kc * 8 + tg]);
            af[2] = __float_as_uint(Qs[rA * QSP + kc * 8 + tg + 4]);
            af[3] = __float_as_uint(Qs[(rA + 8) * QSP + kc * 8 + tg + 4]);
            #pragma unroll
            for (int nt = 0; nt < 4; nt++) {
                int kvr = kh * 32 + nt * 8 + g;
                uint32_t bf[2];
                bf[0] = __float_as_uint(Ks[kvr * KSP + kc * 8 + tg]);
                bf[1] = __float_as_uint(Ks[kvr * KSP + kc * 8 + tg + 4]);
                mma_tf32(sc[nt], af, bf);
            }
        }

        if (j == jend) {
            #pragma unroll
            for (int nt = 0; nt < 4; nt++) {
                int colb = k0 + kh * 32 + nt * 8 + 2 * tg;
                int row0g = q0 + rA, row1g = q0 + rA + 8;
                if (colb     > row0g) sc[nt][0] = -INFINITY;
                if (colb + 1 > row0g) sc[nt][1] = -INFINITY;
                if (colb     > row1g) sc[nt][2] = -INFINITY;
                if (colb + 1 > row1g) sc[nt][3] = -INFINITY;
            }
        }

        float ml0 = -INFINITY, ml1 = -INFINITY;
        #pragma unroll
        for (int nt = 0; nt < 4; nt++) {
            ml0 = fmaxf(ml0, fmaxf(sc[nt][0], sc[nt][1]));
            ml1 = fmaxf(ml1, fmaxf(sc[nt][2], sc[nt][3]));
        }
        ml0 = fmaxf(ml0, __shfl_xor_sync(0xffffffffu, ml0, 1));
        ml0 = fmaxf(ml0, __shfl_xor_sync(0xffffffffu, ml0, 2));
        ml1 = fmaxf(ml1, __shfl_xor_sync(0xffffffffu, ml1, 1));
        ml1 = fmaxf(ml1, __shfl_xor_sync(0xffffffffu, ml1, 2));
        float mn0 = fmaxf(m0, ml0), mn1 = fmaxf(m1, ml1);
        float mr0 = (mn0 == -INFINITY) ? 0.f : mn0;
        float mr1 = (mn1 == -INFINITY) ? 0.f : mn1;
        float a0 = __expf(m0 - mr0);
        float a1 = __expf(m1 - mr1);

        float ll0 = 0.f, ll1 = 0.f;
        #pragma unroll
        for (int nt = 0; nt < 4; nt++) {
            float p0 = __expf(sc[nt][0] - mr0);
            float p1 = __expf(sc[nt][1] - mr0);
            float p2 = __expf(sc[nt][2] - mr1);
            float p3 = __expf(sc[nt][3] - mr1);
            ll0 += p0 + p1;
            ll1 += p2 + p3;
            int cb = kh * 32 + nt * 8 + 2 * tg;
            *(float2*)&Ps[rA * PSP + cb]       = make_float2(f2tf32f(p0), f2tf32f(p1));
            *(float2*)&Ps[(rA + 8) * PSP + cb] = make_float2(f2tf32f(p2), f2tf32f(p3));
        }
        ll0 += __shfl_xor_sync(0xffffffffu, ll0, 1);
        ll0 += __shfl_xor_sync(0xffffffffu, ll0, 2);
        ll1 += __shfl_xor_sync(0xffffffffu, ll1, 1);
        ll1 += __shfl_xor_sync(0xffffffffu, ll1, 2);

        m0 = mn0; m1 = mn1;
        l0 = l0 * a0 + ll0;
        l1 = l1 * a1 + ll1;

        #pragma unroll
        for (int nt = 0; nt < 16; nt++) {
            acc[nt][0] *= a0; acc[nt][1] *= a0;
            acc[nt][2] *= a1; acc[nt][3] *= a1;
        }
        __syncwarp();

        #pragma unroll
        for (int kc = 0; kc < 4; kc++) {
            uint32_t af[4];
            int pc = kh * 32 + kc * 8;
            af[0] = __float_as_uint(Ps[rA * PSP + pc + tg]);
            af[1] = __float_as_uint(Ps[(rA + 8) * PSP + pc + tg]);
            af[2] = __float_as_uint(Ps[rA * PSP + pc + tg + 4]);
            af[3] = __float_as_uint(Ps[(rA + 8) * PSP + pc + tg + 4]);
            int kv0 = kh * 32 + kc * 8 + tg;
            #pragma unroll
            for (int nt = 0; nt < 16; nt++) {
                uint32_t bf[2];
                bf[0] = __float_as_uint(Vs[kv0 * VSP + nt * 8 + g]);
                bf[1] = __float_as_uint(Vs[(kv0 + 4) * VSP + nt * 8 + g]);
                mma_tf32(acc[nt], af, bf);
            }
        }
        __syncwarp();
    }

    // ---- merge kv halves; write tf32-rounded O (plain layout) ----
    __syncthreads();
    float* Osh = Ks;
    float* msh = Ps;
    float* lsh = Ps + 64;

    if (kh == 1) {
        if (tg == 0) {
            msh[rA] = m0;  msh[rA + 8] = m1;
            lsh[rA] = l0;  lsh[rA + 8] = l1;
        }
        #pragma unroll
        for (int nt = 0; nt < 16; nt++) {
            int cb = nt * 8 + 2 * tg;
            *(float2*)&Osh[rA * OSP + cb]       = make_float2(acc[nt][0], acc[nt][1]);
            *(float2*)&Osh[(rA + 8) * OSP + cb] = make_float2(acc[nt][2], acc[nt][3]);
        }
    }
    __syncthreads();
    if (kh == 0) {
        float mB0 = msh[rA], mB1 = msh[rA + 8];
        float lB0 = lsh[rA], lB1 = lsh[rA + 8];
        float mm0 = fmaxf(m0, mB0), mm1 = fmaxf(m1, mB1);
        float wA0 = __expf(m0 - mm0),  wB0 = __expf(mB0 - mm0);
        float wA1 = __expf(m1 - mm1),  wB1 = __expf(mB1 - mm1);
        float inv0 = 1.f / (wA0 * l0 + wB0 * lB0);
        float inv1 = 1.f / (wA1 * l1 + wB1 * lB1);

        size_t ob0 = (((size_t)(b * SS + q0 + rA)) * HH + h) * VHD;
        size_t ob1 = (((size_t)(b * SS + q0 + rA + 8)) * HH + h) * VHD;
        #pragma unroll
        for (int nt = 0; nt < 16; nt++) {
            int cb = nt * 8 + 2 * tg;
            float2 oB0 = *(float2*)&Osh[rA * OSP + cb];
            float2 oB1 = *(float2*)&Osh[(rA + 8) * OSP + cb];
            float2 r0, r1;
            r0.x = f2tf32f((wA0 * acc[nt][0] + wB0 * oB0.x) * inv0);
            r0.y = f2tf32f((wA0 * acc[nt][1] + wB0 * oB0.y) * inv0);
            r1.x = f2tf32f((wA1 * acc[nt][2] + wB1 * oB1.x) * inv1);
            r1.y = f2tf32f((wA1 * acc[nt][3] + wB1 * oB1.y) * inv1);
            *(float2*)&O[ob0 + cb] = r0;
            *(float2*)&O[ob1 + cb] = r1;
        }
    }
}

// ---------------- launch -----------------------------------------------------
extern "C" void kernel_launch(void* const* d_in, const int* in_sizes, int n_in,
                              void* d_out, int out_size)
{
    const float* x       = (const float*)d_in[0];
    const float* wq_w    = (const float*)d_in[1];
    const float* wq_b    = (const float*)d_in[2];
    const float* wkv_a_w = (const float*)d_in[3];
    const float* wkv_a_b = (const float*)d_in[4];
    const float* kvn_g   = (const float*)d_in[5];
    const float* kvn_b   = (const float*)d_in[6];
    const float* wk_w    = (const float*)d_in[7];
    const float* wk_b    = (const float*)d_in[8];
    const float* wv_w    = (const float*)d_in[9];
    const float* wv_b    = (const float*)d_in[10];
    const float* wo_w    = (const float*)d_in[11];
    const float* wo_b    = (const float*)d_in[12];
    const float* cosT    = (const float*)d_in[13];
    const float* sinT    = (const float*)d_in[14];
    float* out = (float*)d_out;

    float *gq, *gkv, *gc, *gkn, *gv, *gK, *gO;
    float *xt, *wqt, *wkvt, *wkt, *wvt, *wot;
    cudaGetSymbolAddress((void**)&gq,   g_q);
    cudaGetSymbolAddress((void**)&gkv,  g_kv);
    cudaGetSymbolAddress((void**)&gc,   g_c);
    cudaGetSymbolAddress((void**)&gkn,  g_kn);
    cudaGetSymbolAddress((void**)&gv,   g_v);
    cudaGetSymbolAddress((void**)&gK,   g_K);
    cudaGetSymbolAddress((void**)&gO,   g_O);
    cudaGetSymbolAddress((void**)&xt,   g_xt);
    cudaGetSymbolAddress((void**)&wqt,  g_wqt);
    cudaGetSymbolAddress((void**)&wkvt, g_wkvt);
    cudaGetSymbolAddress((void**)&wkt,  g_wkt);
    cudaGetSymbolAddress((void**)&wvt,  g_wvt);
    cudaGetSymbolAddress((void**)&wot,  g_wot);

    cudaFuncSetAttribute(gemm_tf32_kernel, cudaFuncAttributeMaxDynamicSharedMemorySize, (int)GEMM_SMEM);
    cudaFuncSetAttribute(attn_mma_kernel, cudaFuncAttributeMaxDynamicSharedMemorySize, (int)ATTN_SMEM);

    // 0a) tf32-round x (plain layout)
    {
        int n4 = ROWS * DIM / 4;
        tf32_convert_kernel<<<(n4 + 255) / 256, 256>>>(x, xt, n4);
    }
    // 0b) transpose+round+permute weights  W[K][N] -> Wt[N][K]
    transpose_w_kernel<<<dim3(QCOLS/32,  DIM/32),    256>>>(wq_w,    wqt,  DIM,    QCOLS);
    transpose_w_kernel<<<dim3(KVCOLS/32, DIM/32),    256>>>(wkv_a_w, wkvt, DIM,    KVCOLS);
    transpose_w_kernel<<<dim3((HH*NOPE)/32, KVRANK/32), 256>>>(wk_w, wkt,  KVRANK, HH*NOPE);
    transpose_w_kernel<<<dim3((HH*VHD)/32,  KVRANK/32), 256>>>(wv_w, wvt,  KVRANK, HH*VHD);
    transpose_w_kernel<<<dim3(DIM/32, (HH*VHD)/32),  256>>>(wo_w,    wot,  HH*VHD, DIM);

    // 1) q = x @ wq_w + b
    gemm_tf32_kernel<<<dim3(QCOLS/GBN, ROWS/GBM), 256, GEMM_SMEM>>>(wqt, xt, wq_b, gq, ROWS, QCOLS, DIM);
    // 2) kv = x @ wkv_a_w + b
    gemm_tf32_kernel<<<dim3(KVCOLS/GBN, ROWS/GBM), 256, GEMM_SMEM>>>(wkvt, xt, wkv_a_b, gkv, ROWS, KVCOLS, DIM);
    // 3) layernorm (tf32 output)
    ln_kernel<<<ROWS, 128>>>(gkv, kvn_g, kvn_b, gc);
    // 4) k_nope = c @ wk_w + b
    gemm_tf32_kernel<<<dim3((HH*NOPE)/GBN, ROWS/GBM), 256, GEMM_SMEM>>>(wkt, gc, wk_b, gkn, ROWS, HH*NOPE, KVRANK);
    // 5) v = c @ wv_w + b
    gemm_tf32_kernel<<<dim3((HH*VHD)/GBN, ROWS/GBM), 256, GEMM_SMEM>>>(wvt, gc, wv_b, gv, ROWS, HH*VHD, KVRANK);
    // 6) rope + assemble K
    {
        int total = ROWS * HH * 32;
        rope_assemble_kernel<<<(total + 255) / 256, 256>>>(gq, gkv, gkn, cosT, sinT, gK);
    }
    // 7) attention (tf32 mma)
    attn_mma_kernel<<<dim3(SS/ABQ, HH, BB), 256, ATTN_SMEM>>>(gq, gK, gv, gO);
    // 8) out = O @ wo_w + b
    gemm_tf32_kernel<<<dim3(DIM/GBN, ROWS/GBM), 256, GEMM_SMEM>>>(wot, gO, wo_b, out, ROWS, DIM, HH*VHD);
}